// round 1
// baseline (speedup 1.0000x reference)
#include <cuda_runtime.h>

// SWT (a-trous) db4, 3 levels, T=4096, rows = 64*32 = 2048.
// out[row][t] = float4{ lo3, hi3, hi2, hi1 }
//
// out_lvl[t] = sum_j dec[j] * in[(t + (4-j)*dil) & 4095],  dil = 1,2,4

#define T_LEN 4096
#define T_MASK 4095
#define NTHREADS 512
#define ELEMS_PER_THREAD (T_LEN / NTHREADS)  // 8

__global__ __launch_bounds__(NTHREADS, 4)
void swt_db4_kernel(const float* __restrict__ x,
                    const float* __restrict__ dec_lo,
                    const float* __restrict__ dec_hi,
                    float4* __restrict__ out)
{
    __shared__ float bufx[T_LEN];
    __shared__ float lo1[T_LEN];
    __shared__ float lo2[T_LEN];

    const int row = blockIdx.x;
    const int tid = threadIdx.x;

    // Filters into registers (broadcast loads, L1-resident after first CTA).
    float flo[8], fhi[8];
#pragma unroll
    for (int j = 0; j < 8; j++) {
        flo[j] = dec_lo[j];
        fhi[j] = dec_hi[j];
    }

    // ---- Load row into smem (float4, fully coalesced) ----
    const float4* x4 = reinterpret_cast<const float4*>(x + (size_t)row * T_LEN);
    float4* bufx4 = reinterpret_cast<float4*>(bufx);
#pragma unroll
    for (int i = 0; i < T_LEN / 4 / NTHREADS; i++) {
        bufx4[tid + i * NTHREADS] = x4[tid + i * NTHREADS];
    }
    __syncthreads();

    // ---- Level 0 lowpass: lo1 = conv(bufx, dec_lo, dil=1) ----
#pragma unroll
    for (int i = 0; i < ELEMS_PER_THREAD; i++) {
        const int t = tid + i * NTHREADS;
        float acc = 0.0f;
#pragma unroll
        for (int j = 0; j < 8; j++)
            acc += flo[j] * bufx[(t + (4 - j)) & T_MASK];
        lo1[t] = acc;
    }
    __syncthreads();

    // ---- Level 1 lowpass: lo2 = conv(lo1, dec_lo, dil=2) ----
#pragma unroll
    for (int i = 0; i < ELEMS_PER_THREAD; i++) {
        const int t = tid + i * NTHREADS;
        float acc = 0.0f;
#pragma unroll
        for (int j = 0; j < 8; j++)
            acc += flo[j] * lo1[(t + (4 - j) * 2) & T_MASK];
        lo2[t] = acc;
    }
    __syncthreads();

    // ---- Final pass: hi1 (from bufx, dil=1), hi2 (from lo1, dil=2),
    //      lo3 & hi3 (from lo2, dil=4). One coalesced float4 store per t. ----
    float4* out_row = out + (size_t)row * T_LEN;
#pragma unroll
    for (int i = 0; i < ELEMS_PER_THREAD; i++) {
        const int t = tid + i * NTHREADS;

        float hi1 = 0.0f, hi2 = 0.0f, lo3 = 0.0f, hi3 = 0.0f;
#pragma unroll
        for (int j = 0; j < 8; j++) {
            hi1 += fhi[j] * bufx[(t + (4 - j)) & T_MASK];
        }
#pragma unroll
        for (int j = 0; j < 8; j++) {
            hi2 += fhi[j] * lo1[(t + (4 - j) * 2) & T_MASK];
        }
#pragma unroll
        for (int j = 0; j < 8; j++) {
            const float v = lo2[(t + (4 - j) * 4) & T_MASK];
            lo3 += flo[j] * v;
            hi3 += fhi[j] * v;
        }

        out_row[t] = make_float4(lo3, hi3, hi2, hi1);
    }
}

extern "C" void kernel_launch(void* const* d_in, const int* in_sizes, int n_in,
                              void* d_out, int out_size)
{
    const float* x      = (const float*)d_in[0];
    const float* dec_lo = (const float*)d_in[1];
    const float* dec_hi = (const float*)d_in[2];
    float4* out         = (float4*)d_out;

    const int rows = in_sizes[0] / T_LEN;  // 64*32 = 2048

    swt_db4_kernel<<<rows, NTHREADS>>>(x, dec_lo, dec_hi, out);
}

// round 3
// speedup vs baseline: 1.2529x; 1.2529x over previous
#include <cuda_runtime.h>

// SWT (a-trous) db4, 3 levels, T=4096, rows = 2048.
// out[row][t] = float4{ lo3, hi3, hi2, hi1 }
// out_lvl[t] = sum_j dec[j] * in[(t + (4-j)*dil) mod 4096], dil = 1,2,4
//
// V2 (resubmit after infra failure): fused lo+hi per level (input read ONCE
// per level), hi1/hi2 carried in registers, halo-padded smem (no per-access
// mask -> immediate-offset LDS), 2 smem buffers (lo2 reuses the x buffer),
// streaming stores.

#define T_LEN    4096
#define HALO     16                    // covers dil=4 offsets [-12, +16]
#define BUF_LEN  (T_LEN + 2 * HALO)    // 4128 floats
#define NTHREADS 512
#define EPT      (T_LEN / NTHREADS)    // 8

__global__ __launch_bounds__(NTHREADS)
void swt_db4_kernel(const float* __restrict__ x,
                    const float* __restrict__ dec_lo,
                    const float* __restrict__ dec_hi,
                    float4* __restrict__ out)
{
    __shared__ float buf0[BUF_LEN];   // x, then lo2
    __shared__ float buf1[BUF_LEN];   // lo1

    const int row = blockIdx.x;
    const int tid = threadIdx.x;

    float flo[8], fhi[8];
#pragma unroll
    for (int j = 0; j < 8; j++) {
        flo[j] = __ldg(&dec_lo[j]);
        fhi[j] = __ldg(&dec_hi[j]);
    }

    // ---- Load row into buf0 (+halo copies written by the loading thread) ----
    const float4* x4 = reinterpret_cast<const float4*>(x + (size_t)row * T_LEN);
#pragma unroll
    for (int i = 0; i < T_LEN / 4 / NTHREADS; i++) {      // 2 iterations
        const int w  = tid + i * NTHREADS;                 // float4 index
        const int t0 = w * 4;
        const float4 v = x4[w];
        *reinterpret_cast<float4*>(&buf0[HALO + t0]) = v;
        if (t0 >= T_LEN - HALO)   // left halo <- tail
            *reinterpret_cast<float4*>(&buf0[t0 - (T_LEN - HALO)]) = v;
        if (t0 < HALO)            // right halo <- head
            *reinterpret_cast<float4*>(&buf0[HALO + T_LEN + t0]) = v;
    }
    __syncthreads();

    // ---- Level 0 (dil=1): read x once, compute lo1 (->buf1) and hi1 (regs) ----
    float hi1r[EPT];
#pragma unroll
    for (int i = 0; i < EPT; i++) {
        const int t = tid + i * NTHREADS;
        const float* b = &buf0[HALO + t];
        float alo = 0.0f, ahi = 0.0f;
#pragma unroll
        for (int j = 0; j < 8; j++) {
            const float v = b[4 - j];
            alo += flo[j] * v;
            ahi += fhi[j] * v;
        }
        hi1r[i] = ahi;
        buf1[HALO + t] = alo;
        if (t >= T_LEN - HALO) buf1[t - (T_LEN - HALO)] = alo;
        if (t < HALO)          buf1[HALO + T_LEN + t]   = alo;
    }
    __syncthreads();

    // ---- Level 1 (dil=2): read lo1 once, compute lo2 (->buf0) and hi2 (regs) ----
    float hi2r[EPT];
#pragma unroll
    for (int i = 0; i < EPT; i++) {
        const int t = tid + i * NTHREADS;
        const float* b = &buf1[HALO + t];
        float alo = 0.0f, ahi = 0.0f;
#pragma unroll
        for (int j = 0; j < 8; j++) {
            const float v = b[(4 - j) * 2];
            alo += flo[j] * v;
            ahi += fhi[j] * v;
        }
        hi2r[i] = ahi;
        buf0[HALO + t] = alo;
        if (t >= T_LEN - HALO) buf0[t - (T_LEN - HALO)] = alo;
        if (t < HALO)          buf0[HALO + T_LEN + t]   = alo;
    }
    __syncthreads();

    // ---- Level 2 (dil=4): read lo2 once, emit one float4 per t (streaming) ----
    float4* out_row = out + (size_t)row * T_LEN;
#pragma unroll
    for (int i = 0; i < EPT; i++) {
        const int t = tid + i * NTHREADS;
        const float* b = &buf0[HALO + t];
        float lo3 = 0.0f, hi3 = 0.0f;
#pragma unroll
        for (int j = 0; j < 8; j++) {
            const float v = b[(4 - j) * 4];
            lo3 += flo[j] * v;
            hi3 += fhi[j] * v;
        }
        __stcs(&out_row[t], make_float4(lo3, hi3, hi2r[i], hi1r[i]));
    }
}

extern "C" void kernel_launch(void* const* d_in, const int* in_sizes, int n_in,
                              void* d_out, int out_size)
{
    const float* x      = (const float*)d_in[0];
    const float* dec_lo = (const float*)d_in[1];
    const float* dec_hi = (const float*)d_in[2];
    float4* out         = (float4*)d_out;

    const int rows = in_sizes[0] / T_LEN;  // 2048

    swt_db4_kernel<<<rows, NTHREADS>>>(x, dec_lo, dec_hi, out);
}